// round 3
// baseline (speedup 1.0000x reference)
#include <cuda_runtime.h>
#include <cuda_bf16.h>

// ---------------------------------------------------------------------------
// BiLSTM-CRF forward loss.  B=64, T=512, V=50000, E=256, H=256, L=9.
// Pipeline: embed -> gemm(gx,l0) -> lstm(l0) -> gemm(gx,l1) -> lstm(l1)
//           -> linear(emissions) -> CRF NLL -> scalar mean.
// ---------------------------------------------------------------------------

#define Bsz  64
#define Tlen 512
#define Emb  256
#define Hd   256
#define Lnum 9
#define BT   (Bsz * Tlen)   // 32768

// -------------------- scratch (device globals; no allocs) -------------------
__device__ float g_x0[(size_t)BT * Emb];            // 33.5 MB  embedded input
__device__ float g_gx[2ull * BT * 1024];            // 268 MB   per-dir input projections
__device__ float g_y0[(size_t)BT * 512];            // 67 MB    layer0 output [fwd|bwd]
__device__ float g_y1[(size_t)BT * 512];            // 67 MB    layer1 output
__device__ float g_wt0[2 * 256 * 1024];             // w_hh0 transposed [d][k][4H]
__device__ float g_wt1[2 * 256 * 1024];             // w_hh1 transposed
__device__ float g_em[(size_t)BT * Lnum];           // emissions
__device__ float g_partial[Bsz];                    // per-batch (logZ - score)

__device__ __forceinline__ float sigm(float x) { return 1.0f / (1.0f + __expf(-x)); }

__device__ __forceinline__ void fma4(float4& acc, const float4 wv, const float s) {
    acc.x = fmaf(wv.x, s, acc.x);
    acc.y = fmaf(wv.y, s, acc.y);
    acc.z = fmaf(wv.z, s, acc.z);
    acc.w = fmaf(wv.w, s, acc.w);
}

// -------------------- 1) embedding gather (float4) --------------------------
__global__ void k_embed(const int* __restrict__ ids, const float* __restrict__ emb) {
    int i = blockIdx.x * blockDim.x + threadIdx.x;      // float4 index
    if (i >= BT * (Emb / 4)) return;
    int pos = i >> 6;            // / (Emb/4)
    int e4  = i & 63;
    ((float4*)g_x0)[i] = ((const float4*)emb)[(size_t)ids[pos] * (Emb / 4) + e4];
}

// -------------------- 2) transpose w_hh [2][1024][256] -> [2][256][1024] ----
__global__ void k_trans(const float* __restrict__ w, int layer) {
    int i = blockIdx.x * blockDim.x + threadIdx.x;      // over 2*1024*256
    if (i >= 2 * 1024 * 256) return;
    int d   = i >> 18;
    int rem = i & 262143;
    int r   = rem >> 8;
    int k   = rem & 255;
    float* dst = layer ? g_wt1 : g_wt0;
    dst[d * 262144 + k * 1024 + r] = w[i];
}

// -------------------- 3) gx GEMM: C[d][m][n] = A[m][:] . W[d][n][:] + b[d][n]
// BM=BN=128, BK=16, 256 threads, 8x8 register tile.
__global__ void __launch_bounds__(256) k_gemm(const float* __restrict__ W,
                                              const float* __restrict__ bias,
                                              int layer) {
    __shared__ float As[16][128];
    __shared__ float Ws[16][128];
    const int K = layer ? 512 : 256;
    const float* __restrict__ Ad = layer ? g_y0 : g_x0;
    const int tid = threadIdx.x;
    const int tx = tid & 15, ty = tid >> 4;
    const int m0 = blockIdx.y * 128, n0 = blockIdx.x * 128;
    const int d = blockIdx.z;
    const float* Wd = W + (size_t)d * 1024 * K;
    const float* bd = bias + d * 1024;
    float* Cd = g_gx + (size_t)d * BT * 1024;
    const int lr = tid >> 2;          // 0..63
    const int lc = (tid & 3) * 4;     // 0,4,8,12

    float acc[8][8];
#pragma unroll
    for (int i = 0; i < 8; i++)
#pragma unroll
        for (int j = 0; j < 8; j++) acc[i][j] = 0.0f;

    for (int k0 = 0; k0 < K; k0 += 16) {
        float4 a0 = *(const float4*)&Ad[(size_t)(m0 + lr) * K + k0 + lc];
        float4 a1 = *(const float4*)&Ad[(size_t)(m0 + lr + 64) * K + k0 + lc];
        float4 w0 = *(const float4*)&Wd[(size_t)(n0 + lr) * K + k0 + lc];
        float4 w1 = *(const float4*)&Wd[(size_t)(n0 + lr + 64) * K + k0 + lc];
        __syncthreads();
        As[lc + 0][lr] = a0.x; As[lc + 1][lr] = a0.y; As[lc + 2][lr] = a0.z; As[lc + 3][lr] = a0.w;
        As[lc + 0][lr + 64] = a1.x; As[lc + 1][lr + 64] = a1.y; As[lc + 2][lr + 64] = a1.z; As[lc + 3][lr + 64] = a1.w;
        Ws[lc + 0][lr] = w0.x; Ws[lc + 1][lr] = w0.y; Ws[lc + 2][lr] = w0.z; Ws[lc + 3][lr] = w0.w;
        Ws[lc + 0][lr + 64] = w1.x; Ws[lc + 1][lr + 64] = w1.y; Ws[lc + 2][lr + 64] = w1.z; Ws[lc + 3][lr + 64] = w1.w;
        __syncthreads();
#pragma unroll
        for (int kk = 0; kk < 16; kk++) {
            float4 af0 = *(const float4*)&As[kk][ty * 8];
            float4 af1 = *(const float4*)&As[kk][ty * 8 + 4];
            float4 wf0 = *(const float4*)&Ws[kk][tx * 8];
            float4 wf1 = *(const float4*)&Ws[kk][tx * 8 + 4];
            float a[8] = {af0.x, af0.y, af0.z, af0.w, af1.x, af1.y, af1.z, af1.w};
            float w[8] = {wf0.x, wf0.y, wf0.z, wf0.w, wf1.x, wf1.y, wf1.z, wf1.w};
#pragma unroll
            for (int i = 0; i < 8; i++)
#pragma unroll
                for (int j = 0; j < 8; j++) acc[i][j] = fmaf(a[i], w[j], acc[i][j]);
        }
    }
    float bv[8];
#pragma unroll
    for (int j = 0; j < 8; j++) bv[j] = bd[n0 + tx * 8 + j];
#pragma unroll
    for (int i = 0; i < 8; i++) {
        int m = m0 + ty * 8 + i;
        float4 o0 = make_float4(acc[i][0] + bv[0], acc[i][1] + bv[1], acc[i][2] + bv[2], acc[i][3] + bv[3]);
        float4 o1 = make_float4(acc[i][4] + bv[4], acc[i][5] + bv[5], acc[i][6] + bv[6], acc[i][7] + bv[7]);
        *(float4*)&Cd[(size_t)m * 1024 + n0 + tx * 8] = o0;
        *(float4*)&Cd[(size_t)m * 1024 + n0 + tx * 8 + 4] = o1;
    }
}

// -------------------- 4) LSTM recurrence (batch-partitioned, no comm) -------
// grid = 32 blocks: dir = bx>>4 (0 fwd, 1 bwd), batch group of 4 per block.
// Each step: gates[4][1024] = h @ W_hh^T (W streamed from L2, transposed
// layout [k][1024]) + gx, then elementwise c/h update, h written to y.
__global__ void __launch_bounds__(256) k_lstm(int layer) {
    __shared__ float hbuf[4][256];
    __shared__ float cbuf[4][256];
    __shared__ float gsm[4][1024];
    const int tid = threadIdx.x;
    const int d  = blockIdx.x >> 4;
    const int b0 = (blockIdx.x & 15) * 4;
    const float* wt = layer ? g_wt1 : g_wt0;
    float* y = layer ? g_y1 : g_y0;
    const float4* wp = reinterpret_cast<const float4*>(wt + d * 262144) + tid;  // row k at wp[k*256]
    const float* gxd = g_gx + (size_t)d * BT * 1024;

#pragma unroll
    for (int b = 0; b < 4; b++) { hbuf[b][tid] = 0.0f; cbuf[b][tid] = 0.0f; }
    __syncthreads();

    for (int s = 0; s < Tlen; s++) {
        const int t = d ? (Tlen - 1 - s) : s;
        float4 a0 = make_float4(0, 0, 0, 0), a1 = a0, a2 = a0, a3 = a0;
#pragma unroll 4
        for (int k = 0; k < 256; k += 4) {
            float4 w0 = wp[(k + 0) * 256];
            float4 w1 = wp[(k + 1) * 256];
            float4 w2 = wp[(k + 2) * 256];
            float4 w3 = wp[(k + 3) * 256];
            float4 h0 = *(const float4*)&hbuf[0][k];
            float4 h1 = *(const float4*)&hbuf[1][k];
            float4 h2 = *(const float4*)&hbuf[2][k];
            float4 h3 = *(const float4*)&hbuf[3][k];
            fma4(a0, w0, h0.x); fma4(a0, w1, h0.y); fma4(a0, w2, h0.z); fma4(a0, w3, h0.w);
            fma4(a1, w0, h1.x); fma4(a1, w1, h1.y); fma4(a1, w2, h1.z); fma4(a1, w3, h1.w);
            fma4(a2, w0, h2.x); fma4(a2, w1, h2.y); fma4(a2, w2, h2.z); fma4(a2, w3, h2.w);
            fma4(a3, w0, h3.x); fma4(a3, w1, h3.y); fma4(a3, w2, h3.z); fma4(a3, w3, h3.w);
        }
        const int r4 = tid * 4;
        {
            float4 g0 = *(const float4*)&gxd[((size_t)(b0 + 0) * Tlen + t) * 1024 + r4];
            float4 g1 = *(const float4*)&gxd[((size_t)(b0 + 1) * Tlen + t) * 1024 + r4];
            float4 g2 = *(const float4*)&gxd[((size_t)(b0 + 2) * Tlen + t) * 1024 + r4];
            float4 g3 = *(const float4*)&gxd[((size_t)(b0 + 3) * Tlen + t) * 1024 + r4];
            a0.x += g0.x; a0.y += g0.y; a0.z += g0.z; a0.w += g0.w;
            a1.x += g1.x; a1.y += g1.y; a1.z += g1.z; a1.w += g1.w;
            a2.x += g2.x; a2.y += g2.y; a2.z += g2.z; a2.w += g2.w;
            a3.x += g3.x; a3.y += g3.y; a3.z += g3.z; a3.w += g3.w;
            *(float4*)&gsm[0][r4] = a0;
            *(float4*)&gsm[1][r4] = a1;
            *(float4*)&gsm[2][r4] = a2;
            *(float4*)&gsm[3][r4] = a3;
        }
        __syncthreads();
#pragma unroll
        for (int bb = 0; bb < 4; bb++) {
            float gi = gsm[bb][tid];
            float gf = gsm[bb][256 + tid];
            float gg = gsm[bb][512 + tid];
            float go = gsm[bb][768 + tid];
            float c = sigm(gf) * cbuf[bb][tid] + sigm(gi) * tanhf(gg);
            float h = sigm(go) * tanhf(c);
            cbuf[bb][tid] = c;
            hbuf[bb][tid] = h;
            y[((size_t)(b0 + bb) * Tlen + t) * 512 + d * 256 + tid] = h;
        }
        __syncthreads();
    }
}

// -------------------- 5) emissions = y1 @ lin_w^T + lin_b -------------------
__global__ void __launch_bounds__(256) k_linear(const float* __restrict__ lw,
                                                const float* __restrict__ lb) {
    __shared__ float ws[Lnum * 512];
    __shared__ float bs[Lnum];
    const int tid = threadIdx.x;
    for (int i = tid; i < Lnum * 512; i += 256) ws[i] = lw[i];
    if (tid < Lnum) bs[tid] = lb[tid];
    __syncthreads();
    const int warp = tid >> 5, lane = tid & 31;
    const int pos = blockIdx.x * 8 + warp;
    const float* yp = g_y1 + (size_t)pos * 512;
    float acc[Lnum];
#pragma unroll
    for (int l = 0; l < Lnum; l++) acc[l] = 0.0f;
    for (int k = lane; k < 512; k += 32) {
        float yv = yp[k];
#pragma unroll
        for (int l = 0; l < Lnum; l++) acc[l] = fmaf(yv, ws[l * 512 + k], acc[l]);
    }
#pragma unroll
    for (int l = 0; l < Lnum; l++)
#pragma unroll
        for (int o = 16; o > 0; o >>= 1) acc[l] += __shfl_xor_sync(0xffffffffu, acc[l], o);
    if (lane < Lnum) g_em[(size_t)pos * Lnum + lane] = acc[lane] + bs[lane];
}

// -------------------- 6) CRF NLL: per-batch logZ and gold score -------------
__global__ void k_crf(const int* __restrict__ labels, const int* __restrict__ mask,
                      const float* __restrict__ trans, const float* __restrict__ startt,
                      const float* __restrict__ endt) {
    const int b = blockIdx.x;
    const int lane = threadIdx.x;
    __shared__ float salpha[Lnum];
    const float* em = g_em + (size_t)b * Tlen * Lnum;
    const int* lab = labels + b * Tlen;
    const int* msk = mask + b * Tlen;
    const int j = (lane < Lnum) ? lane : 0;

    float tr[Lnum];
#pragma unroll
    for (int i = 0; i < Lnum; i++) tr[i] = trans[i * Lnum + j];

    // gold path score (lane-strided over t, then reduced)
    int mcount = 0;
    for (int t = lane; t < Tlen; t += 32) mcount += msk[t];
#pragma unroll
    for (int o = 16; o > 0; o >>= 1) mcount += __shfl_xor_sync(0xffffffffu, mcount, o);
    float sc = 0.0f;
    for (int t = lane + 1; t < Tlen; t += 32)
        if (msk[t]) sc += trans[lab[t - 1] * Lnum + lab[t]] + em[t * Lnum + lab[t]];
#pragma unroll
    for (int o = 16; o > 0; o >>= 1) sc += __shfl_xor_sync(0xffffffffu, sc, o);

    // forward algorithm (alpha over L=9 states, one per lane)
    float alpha = startt[j] + em[j];
    for (int t = 1; t < Tlen; t++) {
        if (lane < Lnum) salpha[lane] = alpha;
        __syncwarp();
        float vs[Lnum];
        float m = -1e30f;
#pragma unroll
        for (int i = 0; i < Lnum; i++) {
            vs[i] = salpha[i] + tr[i];
            m = fmaxf(m, vs[i]);
        }
        float ssum = 0.0f;
#pragma unroll
        for (int i = 0; i < Lnum; i++) ssum += __expf(vs[i] - m);
        float na = m + __logf(ssum) + em[t * Lnum + j];
        if (msk[t]) alpha = na;
        __syncwarp();
    }
    float v = (lane < Lnum) ? alpha + endt[lane] : -1e30f;
    float mm = v;
#pragma unroll
    for (int o = 16; o > 0; o >>= 1) mm = fmaxf(mm, __shfl_xor_sync(0xffffffffu, mm, o));
    float e = (lane < Lnum) ? __expf(v - mm) : 0.0f;
#pragma unroll
    for (int o = 16; o > 0; o >>= 1) e += __shfl_xor_sync(0xffffffffu, e, o);
    float logZ = mm + __logf(e);

    if (lane == 0) {
        sc += startt[lab[0]] + em[lab[0]] + endt[lab[mcount - 1]];
        g_partial[b] = logZ - sc;
    }
}

// -------------------- 7) mean reduce -> scalar loss --------------------------
__global__ void k_final(float* __restrict__ out) {
    __shared__ float s[Bsz];
    const int tid = threadIdx.x;
    s[tid] = g_partial[tid];
    __syncthreads();
    for (int o = 32; o > 0; o >>= 1) {
        if (tid < o) s[tid] += s[tid + o];
        __syncthreads();
    }
    if (tid == 0) out[0] = s[0] * (1.0f / (float)Bsz);
}

// ---------------------------------------------------------------------------
extern "C" void kernel_launch(void* const* d_in, const int* in_sizes, int n_in,
                              void* d_out, int out_size) {
    (void)in_sizes; (void)n_in; (void)out_size;
    const int*   input_ids = (const int*)d_in[0];
    const int*   attn      = (const int*)d_in[1];
    const int*   labels    = (const int*)d_in[2];
    const float* emb       = (const float*)d_in[3];
    const float* w_ih0     = (const float*)d_in[4];
    const float* w_hh0     = (const float*)d_in[5];
    const float* b0        = (const float*)d_in[6];
    const float* w_ih1     = (const float*)d_in[7];
    const float* w_hh1     = (const float*)d_in[8];
    const float* b1        = (const float*)d_in[9];
    const float* lin_w     = (const float*)d_in[10];
    const float* lin_b     = (const float*)d_in[11];
    const float* trans     = (const float*)d_in[12];
    const float* startt    = (const float*)d_in[13];
    const float* endt      = (const float*)d_in[14];
    float* out = (float*)d_out;

    k_embed<<<(BT * (Emb / 4) + 255) / 256, 256>>>(input_ids, emb);
    k_trans<<<(2 * 1024 * 256 + 255) / 256, 256>>>(w_hh0, 0);
    k_trans<<<(2 * 1024 * 256 + 255) / 256, 256>>>(w_hh1, 1);

    k_gemm<<<dim3(8, 256, 2), 256>>>(w_ih0, b0, 0);
    k_lstm<<<32, 256>>>(0);

    k_gemm<<<dim3(8, 256, 2), 256>>>(w_ih1, b1, 1);
    k_lstm<<<32, 256>>>(1);

    k_linear<<<BT / 8, 256>>>(lin_w, lin_b);
    k_crf<<<Bsz, 32>>>(labels, attn, trans, startt, endt);
    k_final<<<1, 64>>>(out);
}